// round 2
// baseline (speedup 1.0000x reference)
#include <cuda_runtime.h>
#include <math.h>

#define B_ 32
#define S_ 64
#define T_ 64
#define H_ 256
#define SOS 1
#define NBLK 128
#define NTHR 192

// ---------------- scratch (device globals: no allocation allowed) ----------------
__device__ float g_hT[2][H_ * B_];          // hidden state, transposed [j][b], double-buffered
__device__ float g_xT_all[S_ * H_ * B_];    // pre-gathered encoder inputs, [t][j][b]
__device__ float g_xT[H_ * B_];             // decoder x for current step, [j][b]
__device__ float g_EB[B_ * S_ * H_];        // encoder outputs, [b][s][j]
__device__ float g_c0[H_];                  // constant part of comb matmul (emb_sos term + bias)
__device__ float g_probs[B_ * T_];          // gathered probabilities
__device__ unsigned int g_bar_count = 0;
__device__ unsigned int g_bar_gen = 0;

__device__ __forceinline__ float wred(float v) {
#pragma unroll
    for (int o = 16; o > 0; o >>= 1) v += __shfl_xor_sync(0xffffffffu, v, o);
    return v;
}
__device__ __forceinline__ float wmax(float v) {
#pragma unroll
    for (int o = 16; o > 0; o >>= 1) v = fmaxf(v, __shfl_xor_sync(0xffffffffu, v, o));
    return v;
}

// Software grid barrier. Safe: 128 blocks x 192 threads, 1 block/SM, all resident.
__device__ __forceinline__ void grid_barrier() {
    __threadfence();      // make this thread's global writes visible (also flushes stale L1)
    __syncthreads();
    if (threadIdx.x == 0) {
        unsigned gen = *((volatile unsigned int*)&g_bar_gen);
        unsigned old = atomicAdd(&g_bar_count, 1u);
        if (old == NBLK - 1) {
            g_bar_count = 0;
            __threadfence();
            *((volatile unsigned int*)&g_bar_gen) = gen + 1u;
        } else {
            while (*((volatile unsigned int*)&g_bar_gen) == gen) { }
        }
    }
    __syncthreads();
}

__global__ void __launch_bounds__(NTHR, 1)
seq2seq_kernel(const int* __restrict__ ctx_tok, const int* __restrict__ inp_tok,
               const int* __restrict__ tsamp,
               const float* __restrict__ enc_emb,
               const float* __restrict__ enc_Wih, const float* __restrict__ enc_Whh,
               const float* __restrict__ enc_bih, const float* __restrict__ enc_bhh,
               const float* __restrict__ dec_emb,
               const float* __restrict__ W_comb, const float* __restrict__ b_comb,
               const float* __restrict__ dec_Wih, const float* __restrict__ dec_Whh,
               const float* __restrict__ dec_bih, const float* __restrict__ dec_bhh,
               const float* __restrict__ W_out, const float* __restrict__ b_out,
               float* __restrict__ out)
{
    extern __shared__ float sm[];
    float* sE   = sm;            // 16384: enc_outs for this block's b (blocks < 32)
    float* sh   = sm + 16384;    // 8192: staged hT
    float* sx   = sm + 24576;    // 8192: staged xT
    float* sgi  = sm + 32768;    // 192
    float* sgh  = sm + 32960;    // 192
    float* shb  = sm + 33152;    // 256: h[b][:] for attention
    float* satt = sm + 33408;    // 64:  scores / attn weights
    float* sctx = sm + 33472;    // 256
    float* sred = sm + 33728;    // 32

    const int tid  = threadIdx.x;
    const int lane = tid & 31;           // lane = b
    const int w    = tid >> 5;           // warp 0..5
    const int bx   = blockIdx.x;
    const int gate = w % 3;              // 0=r 1=z 2=n (PyTorch GRU chunk order)
    const int jl   = w / 3;
    const int j    = bx * 2 + jl;        // output hidden index 0..255
    const int k    = gate * H_ + j;      // gate-row index 0..767

    // ---------------- precompute (parallel) ----------------
    for (int i = bx * NTHR + tid; i < H_ * B_; i += NBLK * NTHR) g_hT[0][i] = 0.f;

    // gather encoder inputs: xT_all[t][jj][b] = enc_emb[context[b][t]][jj]
    for (int i = bx * NTHR + tid; i < S_ * B_ * H_; i += NBLK * NTHR) {
        int jj = i & (H_ - 1);
        int tb = i >> 8;
        int b  = tb & (B_ - 1);
        int t  = tb >> 5;
        int tok = ctx_tok[b * S_ + t];
        g_xT_all[(t * H_ + jj) * B_ + b] = enc_emb[(size_t)tok * H_ + jj];
    }
    // c0[j'] = b_comb[j'] + sum_jj W_comb[j', jj] * dec_emb[SOS][jj]
    {
        int gw = bx * 6 + w;
        if (gw < H_) {
            float s = 0.f;
#pragma unroll
            for (int m = 0; m < 8; m++) {
                int jj = lane + 32 * m;
                s += __ldg(&W_comb[(size_t)gw * (2 * H_) + jj]) * __ldg(&dec_emb[SOS * H_ + jj]);
            }
            s = wred(s);
            if (lane == 0) g_c0[gw] = s + b_comb[gw];
        }
    }
    grid_barrier();

    int buf = 0;

    const float4* wiE = (const float4*)(enc_Wih + (size_t)k * H_);
    const float4* whE = (const float4*)(enc_Whh + (size_t)k * H_);
    const float4* wiD = (const float4*)(dec_Wih + (size_t)k * H_);
    const float4* whD = (const float4*)(dec_Whh + (size_t)k * H_);
    const float biE = enc_bih[k], bhE = enc_bhh[k];
    const float biD = dec_bih[k], bhD = dec_bhh[k];

    // ---------------- encoder: 64 GRU steps, 1 barrier each ----------------
    for (int t = 0; t < S_; t++) {
        const float* hsrc = g_hT[buf];
        const float* xsrc = g_xT_all + t * H_ * B_;
        for (int i = tid; i < H_ * B_; i += NTHR) { sh[i] = __ldcg(hsrc + i); sx[i] = __ldcg(xsrc + i); }
        __syncthreads();

        float ai = biE, ah = bhE;
#pragma unroll 4
        for (int q = 0; q < H_ / 4; q++) {
            float4 a = __ldg(wiE + q);
            float4 c = __ldg(whE + q);
            int base = q * 4 * B_ + lane;
            ai += a.x * sx[base] + a.y * sx[base + B_] + a.z * sx[base + 2 * B_] + a.w * sx[base + 3 * B_];
            ah += c.x * sh[base] + c.y * sh[base + B_] + c.z * sh[base + 2 * B_] + c.w * sh[base + 3 * B_];
        }
        sgi[w * 32 + lane] = ai; sgh[w * 32 + lane] = ah;
        __syncthreads();
        if (gate == 0) {   // warps 0 and 3 combine their gate triple
            float r = 1.f / (1.f + expf(-(sgi[w * 32 + lane] + sgh[w * 32 + lane])));
            float z = 1.f / (1.f + expf(-(sgi[(w + 1) * 32 + lane] + sgh[(w + 1) * 32 + lane])));
            float n = tanhf(sgi[(w + 2) * 32 + lane] + r * sgh[(w + 2) * 32 + lane]);
            float hold = sh[j * B_ + lane];
            float hn = (1.f - z) * n + z * hold;
            g_hT[buf ^ 1][j * B_ + lane] = hn;
            g_EB[((size_t)lane * S_ + t) * H_ + j] = hn;
        }
        buf ^= 1;
        grid_barrier();
    }

    // ---------------- load this block's enc_outs into SMEM (persists through decode) ----------------
    if (bx < B_) {
        const float* esrc = g_EB + (size_t)bx * S_ * H_;
        for (int i = tid; i < S_ * H_; i += NTHR) sE[i] = __ldcg(esrc + i);
    }

    // ---------------- decoder: 64 steps, 2 barriers each ----------------
    for (int t = 0; t < T_; t++) {
        // ---- phase 1: gh dots (all blocks) + attention/x (blocks 0..31) ----
        const float* hsrc = g_hT[buf];
        for (int i = tid; i < H_ * B_; i += NTHR) sh[i] = __ldcg(hsrc + i);
        __syncthreads();

        float ah = bhD;
#pragma unroll 4
        for (int q = 0; q < H_ / 4; q++) {
            float4 c = __ldg(whD + q);
            int base = q * 4 * B_ + lane;
            ah += c.x * sh[base] + c.y * sh[base + B_] + c.z * sh[base + 2 * B_] + c.w * sh[base + 3 * B_];
        }

        if (bx < B_) {                       // this block owns batch element b = bx
            const int b = bx;
            for (int jj = tid; jj < H_; jj += NTHR) shb[jj] = sh[jj * B_ + b];
            __syncthreads();
            // scores[s] = enc_outs[s,b,:] . h[b,:]
            for (int s = w; s < S_; s += 6) {
                float p = 0.f;
#pragma unroll
                for (int m = 0; m < 8; m++) { int jj = lane + 32 * m; p += sE[s * H_ + jj] * shb[jj]; }
                p = wred(p);
                if (lane == 0) satt[s] = p;
            }
            __syncthreads();
            if (w == 0) {                    // softmax over 64 scores
                float v0 = satt[lane], v1 = satt[lane + 32];
                float mx = wmax(fmaxf(v0, v1));
                float e0 = expf(v0 - mx), e1 = expf(v1 - mx);
                float ssum = wred(e0 + e1);
                satt[lane] = e0 / ssum; satt[lane + 32] = e1 / ssum;
            }
            if (w == 1 && t > 0) {           // prob for previous step (uses h = h_new of step t-1)
                int tok = inp_tok[b * T_ + (t - 1)];
                float p = 0.f;
#pragma unroll
                for (int m = 0; m < 8; m++) { int jj = lane + 32 * m; p += shb[jj] * __ldg(&W_out[(size_t)tok * H_ + jj]); }
                p = wred(p);
                if (lane == 0) g_probs[b * T_ + (t - 1)] = 1.f / (1.f + expf(-(p + b_out[tok])));
            }
            __syncthreads();
            // ctx[jj] = sum_s attn[s] * enc_outs[s,b,jj]
            for (int jj = tid; jj < H_; jj += NTHR) {
                float c = 0.f;
                for (int s = 0; s < S_; s++) c += satt[s] * sE[s * H_ + jj];
                sctx[jj] = c;
            }
            __syncthreads();
            // x[j'] = relu(c0[j'] + W_comb[j', H:2H] . ctx)
            for (int jp = w; jp < H_; jp += 6) {
                const float* wr = W_comb + (size_t)jp * (2 * H_) + H_;
                float p = 0.f;
#pragma unroll
                for (int m = 0; m < 8; m++) { int jj = lane + 32 * m; p += __ldg(wr + jj) * sctx[jj]; }
                p = wred(p);
                if (lane == 0) {
                    float xv = g_c0[jp] + p;
                    g_xT[jp * B_ + b] = xv > 0.f ? xv : 0.f;
                }
            }
        }
        grid_barrier();

        // ---- phase 2: gi dots + GRU combine ----
        for (int i = tid; i < H_ * B_; i += NTHR) sx[i] = __ldcg(g_xT + i);
        __syncthreads();
        float ai = biD;
#pragma unroll 4
        for (int q = 0; q < H_ / 4; q++) {
            float4 a = __ldg(wiD + q);
            int base = q * 4 * B_ + lane;
            ai += a.x * sx[base] + a.y * sx[base + B_] + a.z * sx[base + 2 * B_] + a.w * sx[base + 3 * B_];
        }
        sgi[w * 32 + lane] = ai; sgh[w * 32 + lane] = ah;
        __syncthreads();
        if (gate == 0) {
            float r = 1.f / (1.f + expf(-(sgi[w * 32 + lane] + sgh[w * 32 + lane])));
            float z = 1.f / (1.f + expf(-(sgi[(w + 1) * 32 + lane] + sgh[(w + 1) * 32 + lane])));
            float n = tanhf(sgi[(w + 2) * 32 + lane] + r * sgh[(w + 2) * 32 + lane]);
            float hold = sh[j * B_ + lane];   // sh still holds h_{t} from phase 1
            float hn = (1.f - z) * n + z * hold;
            g_hT[buf ^ 1][j * B_ + lane] = hn;
        }
        buf ^= 1;
        grid_barrier();
    }

    // ---------------- final-step prob ----------------
    if (bx < B_) {
        const int b = bx;
        for (int jj = tid; jj < H_; jj += NTHR) shb[jj] = __ldcg(&g_hT[buf][jj * B_ + b]);
        __syncthreads();
        if (w == 0) {
            int tok = inp_tok[b * T_ + (T_ - 1)];
            float p = 0.f;
#pragma unroll
            for (int m = 0; m < 8; m++) { int jj = lane + 32 * m; p += shb[jj] * __ldg(&W_out[(size_t)tok * H_ + jj]); }
            p = wred(p);
            if (lane == 0) g_probs[b * T_ + (T_ - 1)] = 1.f / (1.f + expf(-(p + b_out[tok])));
        }
    }
    grid_barrier();

    // ---------------- outputs: out[0] = loss, out[1..] = probs [B,T] ----------------
    for (int i = bx * NTHR + tid; i < B_ * T_; i += NBLK * NTHR) out[1 + i] = __ldcg(g_probs + i);
    if (bx == 0) {
        float tv = tsamp ? (float)(*tsamp) : 1.0f;
        float acc = 0.f;
        for (int i = tid; i < B_ * T_; i += NTHR) {
            float p  = __ldcg(g_probs + i);
            float lp = fmaxf(logf(p), -100.f);
            float l1 = fmaxf(log1pf(-p), -100.f);
            acc += tv * lp + (1.f - tv) * l1;
        }
        acc = wred(acc);
        if (lane == 0) sred[w] = acc;
        __syncthreads();
        if (tid == 0) {
            float s = 0.f;
            for (int u = 0; u < 6; u++) s += sred[u];
            out[0] = -s / (float)(B_ * T_);
        }
    }
}

extern "C" void kernel_launch(void* const* d_in, const int* in_sizes, int n_in,
                              void* d_out, int out_size) {
    (void)in_sizes; (void)out_size;
    const size_t smem = 33760 * sizeof(float);   // 135040 B
    cudaFuncSetAttribute(seq2seq_kernel, cudaFuncAttributeMaxDynamicSharedMemorySize, (int)smem);

    // Defensive input indexing: true_sample may or may not be materialized as a tensor.
    int base = (n_in >= 17) ? 3 : 2;
    const int* ts = (n_in >= 17) ? (const int*)d_in[2] : nullptr;

    seq2seq_kernel<<<NBLK, NTHR, smem>>>(
        (const int*)d_in[0], (const int*)d_in[1], ts,
        (const float*)d_in[base + 0],  // enc_emb
        (const float*)d_in[base + 1],  // enc_Wih
        (const float*)d_in[base + 2],  // enc_Whh
        (const float*)d_in[base + 3],  // enc_bih
        (const float*)d_in[base + 4],  // enc_bhh
        (const float*)d_in[base + 5],  // dec_emb
        (const float*)d_in[base + 6],  // W_comb
        (const float*)d_in[base + 7],  // b_comb
        (const float*)d_in[base + 8],  // dec_Wih
        (const float*)d_in[base + 9],  // dec_Whh
        (const float*)d_in[base + 10], // dec_bih
        (const float*)d_in[base + 11], // dec_bhh
        (const float*)d_in[base + 12], // W_out
        (const float*)d_in[base + 13], // b_out
        (float*)d_out);
}

// round 3
// speedup vs baseline: 1.0017x; 1.0017x over previous
#include <cuda_runtime.h>
#include <math.h>

#define B_ 32
#define S_ 64
#define T_ 64
#define H_ 256
#define SOS 1
#define NBLK 128
#define NTHR 192

// ---------------- scratch (device globals: no allocation allowed) ----------------
__device__ float g_hT[2][H_ * B_];          // hidden state, transposed [j][b], double-buffered
__device__ float g_xT_all[S_ * H_ * B_];    // pre-gathered encoder inputs, [t][j][b]
__device__ float g_xT[H_ * B_];             // decoder x for current step, [j][b]
__device__ float g_EB[B_ * S_ * H_];        // encoder outputs, [b][s][j]
__device__ float g_c0[H_];                  // constant part of comb matmul (emb_sos term + bias)
__device__ float g_probs[B_ * T_];          // gathered probabilities
__device__ unsigned int g_bar_count = 0;
__device__ unsigned int g_bar_gen = 0;

__device__ __forceinline__ float wred(float v) {
#pragma unroll
    for (int o = 16; o > 0; o >>= 1) v += __shfl_xor_sync(0xffffffffu, v, o);
    return v;
}
__device__ __forceinline__ float wmax(float v) {
#pragma unroll
    for (int o = 16; o > 0; o >>= 1) v = fmaxf(v, __shfl_xor_sync(0xffffffffu, v, o));
    return v;
}

// Software grid barrier. Safe: 128 blocks x 192 threads, 1 block/SM, all resident.
__device__ __forceinline__ void grid_barrier() {
    __threadfence();      // make this thread's global writes visible (also flushes stale L1)
    __syncthreads();
    if (threadIdx.x == 0) {
        unsigned gen = *((volatile unsigned int*)&g_bar_gen);
        unsigned old = atomicAdd(&g_bar_count, 1u);
        if (old == NBLK - 1) {
            g_bar_count = 0;
            __threadfence();
            *((volatile unsigned int*)&g_bar_gen) = gen + 1u;
        } else {
            while (*((volatile unsigned int*)&g_bar_gen) == gen) { }
        }
    }
    __syncthreads();
}

__global__ void __launch_bounds__(NTHR, 1)
seq2seq_kernel(const int* __restrict__ ctx_tok, const int* __restrict__ inp_tok,
               const int* __restrict__ tsamp,
               const float* __restrict__ enc_emb,
               const float* __restrict__ enc_Wih, const float* __restrict__ enc_Whh,
               const float* __restrict__ enc_bih, const float* __restrict__ enc_bhh,
               const float* __restrict__ dec_emb,
               const float* __restrict__ W_comb, const float* __restrict__ b_comb,
               const float* __restrict__ dec_Wih, const float* __restrict__ dec_Whh,
               const float* __restrict__ dec_bih, const float* __restrict__ dec_bhh,
               const float* __restrict__ W_out, const float* __restrict__ b_out,
               float* __restrict__ out)
{
    extern __shared__ float sm[];
    float* sE   = sm;            // 16384: enc_outs for this block's b (blocks < 32)
    float* sh   = sm + 16384;    // 8192: staged hT
    float* sx   = sm + 24576;    // 8192: staged xT
    float* sgi  = sm + 32768;    // 192
    float* sgh  = sm + 32960;    // 192
    float* shb  = sm + 33152;    // 256: h[b][:] for attention
    float* satt = sm + 33408;    // 64:  scores / attn weights
    float* sctx = sm + 33472;    // 256
    float* sred = sm + 33728;    // 32

    const int tid  = threadIdx.x;
    const int lane = tid & 31;           // lane = b
    const int w    = tid >> 5;           // warp 0..5
    const int bx   = blockIdx.x;
    const int gate = w % 3;              // 0=r 1=z 2=n (PyTorch GRU chunk order)
    const int jl   = w / 3;
    const int j    = bx * 2 + jl;        // output hidden index 0..255
    const int k    = gate * H_ + j;      // gate-row index 0..767

    // ---------------- precompute (parallel) ----------------
    for (int i = bx * NTHR + tid; i < H_ * B_; i += NBLK * NTHR) g_hT[0][i] = 0.f;

    // gather encoder inputs: xT_all[t][jj][b] = enc_emb[context[b][t]][jj]
    for (int i = bx * NTHR + tid; i < S_ * B_ * H_; i += NBLK * NTHR) {
        int jj = i & (H_ - 1);
        int tb = i >> 8;
        int b  = tb & (B_ - 1);
        int t  = tb >> 5;
        int tok = ctx_tok[b * S_ + t];
        g_xT_all[(t * H_ + jj) * B_ + b] = enc_emb[(size_t)tok * H_ + jj];
    }
    // c0[j'] = b_comb[j'] + sum_jj W_comb[j', jj] * dec_emb[SOS][jj]
    {
        int gw = bx * 6 + w;
        if (gw < H_) {
            float s = 0.f;
#pragma unroll
            for (int m = 0; m < 8; m++) {
                int jj = lane + 32 * m;
                s += __ldg(&W_comb[(size_t)gw * (2 * H_) + jj]) * __ldg(&dec_emb[SOS * H_ + jj]);
            }
            s = wred(s);
            if (lane == 0) g_c0[gw] = s + b_comb[gw];
        }
    }
    grid_barrier();

    int buf = 0;

    const float4* wiE = (const float4*)(enc_Wih + (size_t)k * H_);
    const float4* whE = (const float4*)(enc_Whh + (size_t)k * H_);
    const float4* wiD = (const float4*)(dec_Wih + (size_t)k * H_);
    const float4* whD = (const float4*)(dec_Whh + (size_t)k * H_);
    const float biE = enc_bih[k], bhE = enc_bhh[k];
    const float biD = dec_bih[k], bhD = dec_bhh[k];

    // ---------------- encoder: 64 GRU steps, 1 barrier each ----------------
    for (int t = 0; t < S_; t++) {
        const float* hsrc = g_hT[buf];
        const float* xsrc = g_xT_all + t * H_ * B_;
        for (int i = tid; i < H_ * B_; i += NTHR) { sh[i] = __ldcg(hsrc + i); sx[i] = __ldcg(xsrc + i); }
        __syncthreads();

        float ai = biE, ah = bhE;
#pragma unroll 4
        for (int q = 0; q < H_ / 4; q++) {
            float4 a = __ldg(wiE + q);
            float4 c = __ldg(whE + q);
            int base = q * 4 * B_ + lane;
            ai += a.x * sx[base] + a.y * sx[base + B_] + a.z * sx[base + 2 * B_] + a.w * sx[base + 3 * B_];
            ah += c.x * sh[base] + c.y * sh[base + B_] + c.z * sh[base + 2 * B_] + c.w * sh[base + 3 * B_];
        }
        sgi[w * 32 + lane] = ai; sgh[w * 32 + lane] = ah;
        __syncthreads();
        if (gate == 0) {   // warps 0 and 3 combine their gate triple
            float r = 1.f / (1.f + expf(-(sgi[w * 32 + lane] + sgh[w * 32 + lane])));
            float z = 1.f / (1.f + expf(-(sgi[(w + 1) * 32 + lane] + sgh[(w + 1) * 32 + lane])));
            float n = tanhf(sgi[(w + 2) * 32 + lane] + r * sgh[(w + 2) * 32 + lane]);
            float hold = sh[j * B_ + lane];
            float hn = (1.f - z) * n + z * hold;
            g_hT[buf ^ 1][j * B_ + lane] = hn;
            g_EB[((size_t)lane * S_ + t) * H_ + j] = hn;
        }
        buf ^= 1;
        grid_barrier();
    }

    // ---------------- load this block's enc_outs into SMEM (persists through decode) ----------------
    if (bx < B_) {
        const float* esrc = g_EB + (size_t)bx * S_ * H_;
        for (int i = tid; i < S_ * H_; i += NTHR) sE[i] = __ldcg(esrc + i);
    }

    // ---------------- decoder: 64 steps, 2 barriers each ----------------
    for (int t = 0; t < T_; t++) {
        // ---- phase 1: gh dots (all blocks) + attention/x (blocks 0..31) ----
        const float* hsrc = g_hT[buf];
        for (int i = tid; i < H_ * B_; i += NTHR) sh[i] = __ldcg(hsrc + i);
        __syncthreads();

        float ah = bhD;
#pragma unroll 4
        for (int q = 0; q < H_ / 4; q++) {
            float4 c = __ldg(whD + q);
            int base = q * 4 * B_ + lane;
            ah += c.x * sh[base] + c.y * sh[base + B_] + c.z * sh[base + 2 * B_] + c.w * sh[base + 3 * B_];
        }

        if (bx < B_) {                       // this block owns batch element b = bx
            const int b = bx;
            for (int jj = tid; jj < H_; jj += NTHR) shb[jj] = sh[jj * B_ + b];
            __syncthreads();
            // scores[s] = enc_outs[s,b,:] . h[b,:]
            for (int s = w; s < S_; s += 6) {
                float p = 0.f;
#pragma unroll
                for (int m = 0; m < 8; m++) { int jj = lane + 32 * m; p += sE[s * H_ + jj] * shb[jj]; }
                p = wred(p);
                if (lane == 0) satt[s] = p;
            }
            __syncthreads();
            if (w == 0) {                    // softmax over 64 scores
                float v0 = satt[lane], v1 = satt[lane + 32];
                float mx = wmax(fmaxf(v0, v1));
                float e0 = expf(v0 - mx), e1 = expf(v1 - mx);
                float ssum = wred(e0 + e1);
                satt[lane] = e0 / ssum; satt[lane + 32] = e1 / ssum;
            }
            if (w == 1 && t > 0) {           // prob for previous step (uses h = h_new of step t-1)
                int tok = inp_tok[b * T_ + (t - 1)];
                float p = 0.f;
#pragma unroll
                for (int m = 0; m < 8; m++) { int jj = lane + 32 * m; p += shb[jj] * __ldg(&W_out[(size_t)tok * H_ + jj]); }
                p = wred(p);
                if (lane == 0) g_probs[b * T_ + (t - 1)] = 1.f / (1.f + expf(-(p + b_out[tok])));
            }
            __syncthreads();
            // ctx[jj] = sum_s attn[s] * enc_outs[s,b,jj]
            for (int jj = tid; jj < H_; jj += NTHR) {
                float c = 0.f;
                for (int s = 0; s < S_; s++) c += satt[s] * sE[s * H_ + jj];
                sctx[jj] = c;
            }
            __syncthreads();
            // x[j'] = relu(c0[j'] + W_comb[j', H:2H] . ctx)
            for (int jp = w; jp < H_; jp += 6) {
                const float* wr = W_comb + (size_t)jp * (2 * H_) + H_;
                float p = 0.f;
#pragma unroll
                for (int m = 0; m < 8; m++) { int jj = lane + 32 * m; p += __ldg(wr + jj) * sctx[jj]; }
                p = wred(p);
                if (lane == 0) {
                    float xv = g_c0[jp] + p;
                    g_xT[jp * B_ + b] = xv > 0.f ? xv : 0.f;
                }
            }
        }
        grid_barrier();

        // ---- phase 2: gi dots + GRU combine ----
        for (int i = tid; i < H_ * B_; i += NTHR) sx[i] = __ldcg(g_xT + i);
        __syncthreads();
        float ai = biD;
#pragma unroll 4
        for (int q = 0; q < H_ / 4; q++) {
            float4 a = __ldg(wiD + q);
            int base = q * 4 * B_ + lane;
            ai += a.x * sx[base] + a.y * sx[base + B_] + a.z * sx[base + 2 * B_] + a.w * sx[base + 3 * B_];
        }
        sgi[w * 32 + lane] = ai; sgh[w * 32 + lane] = ah;
        __syncthreads();
        if (gate == 0) {
            float r = 1.f / (1.f + expf(-(sgi[w * 32 + lane] + sgh[w * 32 + lane])));
            float z = 1.f / (1.f + expf(-(sgi[(w + 1) * 32 + lane] + sgh[(w + 1) * 32 + lane])));
            float n = tanhf(sgi[(w + 2) * 32 + lane] + r * sgh[(w + 2) * 32 + lane]);
            float hold = sh[j * B_ + lane];   // sh still holds h_{t} from phase 1
            float hn = (1.f - z) * n + z * hold;
            g_hT[buf ^ 1][j * B_ + lane] = hn;
        }
        buf ^= 1;
        grid_barrier();
    }

    // ---------------- final-step prob ----------------
    if (bx < B_) {
        const int b = bx;
        for (int jj = tid; jj < H_; jj += NTHR) shb[jj] = __ldcg(&g_hT[buf][jj * B_ + b]);
        __syncthreads();
        if (w == 0) {
            int tok = inp_tok[b * T_ + (T_ - 1)];
            float p = 0.f;
#pragma unroll
            for (int m = 0; m < 8; m++) { int jj = lane + 32 * m; p += shb[jj] * __ldg(&W_out[(size_t)tok * H_ + jj]); }
            p = wred(p);
            if (lane == 0) g_probs[b * T_ + (T_ - 1)] = 1.f / (1.f + expf(-(p + b_out[tok])));
        }
    }
    grid_barrier();

    // ---------------- outputs: out[0] = loss, out[1..] = probs [B,T] ----------------
    for (int i = bx * NTHR + tid; i < B_ * T_; i += NBLK * NTHR) out[1 + i] = __ldcg(g_probs + i);
    if (bx == 0) {
        float tv = tsamp ? (float)(*tsamp) : 1.0f;
        float acc = 0.f;
        for (int i = tid; i < B_ * T_; i += NTHR) {
            float p  = __ldcg(g_probs + i);
            float lp = fmaxf(logf(p), -100.f);
            float l1 = fmaxf(log1pf(-p), -100.f);
            acc += tv * lp + (1.f - tv) * l1;
        }
        acc = wred(acc);
        if (lane == 0) sred[w] = acc;
        __syncthreads();
        if (tid == 0) {
            float s = 0.f;
            for (int u = 0; u < 6; u++) s += sred[u];
            out[0] = -s / (float)(B_ * T_);
        }
    }
}

extern "C" void kernel_launch(void* const* d_in, const int* in_sizes, int n_in,
                              void* d_out, int out_size) {
    (void)in_sizes; (void)out_size;
    const size_t smem = 33760 * sizeof(float);   // 135040 B
    cudaFuncSetAttribute(seq2seq_kernel, cudaFuncAttributeMaxDynamicSharedMemorySize, (int)smem);

    // Defensive input indexing: true_sample may or may not be materialized as a tensor.
    int base = (n_in >= 17) ? 3 : 2;
    const int* ts = (n_in >= 17) ? (const int*)d_in[2] : nullptr;

    seq2seq_kernel<<<NBLK, NTHR, smem>>>(
        (const int*)d_in[0], (const int*)d_in[1], ts,
        (const float*)d_in[base + 0],  // enc_emb
        (const float*)d_in[base + 1],  // enc_Wih
        (const float*)d_in[base + 2],  // enc_Whh
        (const float*)d_in[base + 3],  // enc_bih
        (const float*)d_in[base + 4],  // enc_bhh
        (const float*)d_in[base + 5],  // dec_emb
        (const float*)d_in[base + 6],  // W_comb
        (const float*)d_in[base + 7],  // b_comb
        (const float*)d_in[base + 8],  // dec_Wih
        (const float*)d_in[base + 9],  // dec_Whh
        (const float*)d_in[base + 10], // dec_bih
        (const float*)d_in[base + 11], // dec_bhh
        (const float*)d_in[base + 12], // W_out
        (const float*)d_in[base + 13], // b_out
        (float*)d_out);
}

// round 4
// speedup vs baseline: 1.0045x; 1.0028x over previous
#include <cuda_runtime.h>
#include <math.h>

#define B_ 32
#define S_ 64
#define T_ 64
#define H_ 256
#define SOS 1
#define NBLK 128
#define NTHR 192

// ---------------- scratch (device globals: no allocation allowed) ----------------
__device__ float g_hT[2][H_ * B_];          // hidden state, transposed [j][b], double-buffered
__device__ float g_xT_all[S_ * H_ * B_];    // pre-gathered encoder inputs, [t][j][b]
__device__ float g_xT[H_ * B_];             // decoder x for current step, [j][b]
__device__ float g_EB[B_ * S_ * H_];        // encoder outputs, [b][s][j]
__device__ float g_c0[H_];                  // constant part of comb matmul (emb_sos term + bias)
__device__ float g_probs[B_ * T_];          // gathered probabilities
__device__ unsigned int g_bar_count = 0;
__device__ unsigned int g_bar_gen = 0;

__device__ __forceinline__ float wred(float v) {
#pragma unroll
    for (int o = 16; o > 0; o >>= 1) v += __shfl_xor_sync(0xffffffffu, v, o);
    return v;
}
__device__ __forceinline__ float wmax(float v) {
#pragma unroll
    for (int o = 16; o > 0; o >>= 1) v = fmaxf(v, __shfl_xor_sync(0xffffffffu, v, o));
    return v;
}

// Software grid barrier. Safe: 128 blocks x 192 threads, 1 block/SM, all resident.
__device__ __forceinline__ void grid_barrier() {
    __threadfence();      // make this thread's global writes visible (also flushes stale L1)
    __syncthreads();
    if (threadIdx.x == 0) {
        unsigned gen = *((volatile unsigned int*)&g_bar_gen);
        unsigned old = atomicAdd(&g_bar_count, 1u);
        if (old == NBLK - 1) {
            g_bar_count = 0;
            __threadfence();
            *((volatile unsigned int*)&g_bar_gen) = gen + 1u;
        } else {
            while (*((volatile unsigned int*)&g_bar_gen) == gen) { }
        }
    }
    __syncthreads();
}

__global__ void __launch_bounds__(NTHR, 1)
seq2seq_kernel(const int* __restrict__ ctx_tok, const int* __restrict__ inp_tok,
               const int* __restrict__ tsamp,
               const float* __restrict__ enc_emb,
               const float* __restrict__ enc_Wih, const float* __restrict__ enc_Whh,
               const float* __restrict__ enc_bih, const float* __restrict__ enc_bhh,
               const float* __restrict__ dec_emb,
               const float* __restrict__ W_comb, const float* __restrict__ b_comb,
               const float* __restrict__ dec_Wih, const float* __restrict__ dec_Whh,
               const float* __restrict__ dec_bih, const float* __restrict__ dec_bhh,
               const float* __restrict__ W_out, const float* __restrict__ b_out,
               float* __restrict__ out)
{
    extern __shared__ float sm[];
    float* sE   = sm;            // 16384: enc_outs for this block's b (blocks < 32)
    float* sh   = sm + 16384;    // 8192: staged hT
    float* sx   = sm + 24576;    // 8192: staged xT
    float* sgi  = sm + 32768;    // 192
    float* sgh  = sm + 32960;    // 192
    float* shb  = sm + 33152;    // 256: h[b][:] for attention
    float* satt = sm + 33408;    // 64:  scores / attn weights
    float* sctx = sm + 33472;    // 256
    float* sred = sm + 33728;    // 32

    const int tid  = threadIdx.x;
    const int lane = tid & 31;           // lane = b
    const int w    = tid >> 5;           // warp 0..5
    const int bx   = blockIdx.x;
    const int gate = w % 3;              // 0=r 1=z 2=n (PyTorch GRU chunk order)
    const int jl   = w / 3;
    const int j    = bx * 2 + jl;        // output hidden index 0..255
    const int k    = gate * H_ + j;      // gate-row index 0..767

    // ---------------- precompute (parallel) ----------------
    for (int i = bx * NTHR + tid; i < H_ * B_; i += NBLK * NTHR) g_hT[0][i] = 0.f;

    // gather encoder inputs: xT_all[t][jj][b] = enc_emb[context[b][t]][jj]
    for (int i = bx * NTHR + tid; i < S_ * B_ * H_; i += NBLK * NTHR) {
        int jj = i & (H_ - 1);
        int tb = i >> 8;
        int b  = tb & (B_ - 1);
        int t  = tb >> 5;
        int tok = ctx_tok[b * S_ + t];
        g_xT_all[(t * H_ + jj) * B_ + b] = enc_emb[(size_t)tok * H_ + jj];
    }
    // c0[j'] = b_comb[j'] + sum_jj W_comb[j', jj] * dec_emb[SOS][jj]
    {
        int gw = bx * 6 + w;
        if (gw < H_) {
            float s = 0.f;
#pragma unroll
            for (int m = 0; m < 8; m++) {
                int jj = lane + 32 * m;
                s += __ldg(&W_comb[(size_t)gw * (2 * H_) + jj]) * __ldg(&dec_emb[SOS * H_ + jj]);
            }
            s = wred(s);
            if (lane == 0) g_c0[gw] = s + b_comb[gw];
        }
    }
    grid_barrier();

    int buf = 0;

    const float4* wiE = (const float4*)(enc_Wih + (size_t)k * H_);
    const float4* whE = (const float4*)(enc_Whh + (size_t)k * H_);
    const float4* wiD = (const float4*)(dec_Wih + (size_t)k * H_);
    const float4* whD = (const float4*)(dec_Whh + (size_t)k * H_);
    const float biE = enc_bih[k], bhE = enc_bhh[k];
    const float biD = dec_bih[k], bhD = dec_bhh[k];

    // ---------------- encoder: 64 GRU steps, 1 barrier each ----------------
    for (int t = 0; t < S_; t++) {
        const float* hsrc = g_hT[buf];
        const float* xsrc = g_xT_all + t * H_ * B_;
        for (int i = tid; i < H_ * B_; i += NTHR) { sh[i] = __ldcg(hsrc + i); sx[i] = __ldcg(xsrc + i); }
        __syncthreads();

        float ai = biE, ah = bhE;
#pragma unroll 4
        for (int q = 0; q < H_ / 4; q++) {
            float4 a = __ldg(wiE + q);
            float4 c = __ldg(whE + q);
            int base = q * 4 * B_ + lane;
            ai += a.x * sx[base] + a.y * sx[base + B_] + a.z * sx[base + 2 * B_] + a.w * sx[base + 3 * B_];
            ah += c.x * sh[base] + c.y * sh[base + B_] + c.z * sh[base + 2 * B_] + c.w * sh[base + 3 * B_];
        }
        sgi[w * 32 + lane] = ai; sgh[w * 32 + lane] = ah;
        __syncthreads();
        if (gate == 0) {   // warps 0 and 3 combine their gate triple
            float r = 1.f / (1.f + expf(-(sgi[w * 32 + lane] + sgh[w * 32 + lane])));
            float z = 1.f / (1.f + expf(-(sgi[(w + 1) * 32 + lane] + sgh[(w + 1) * 32 + lane])));
            float n = tanhf(sgi[(w + 2) * 32 + lane] + r * sgh[(w + 2) * 32 + lane]);
            float hold = sh[j * B_ + lane];
            float hn = (1.f - z) * n + z * hold;
            g_hT[buf ^ 1][j * B_ + lane] = hn;
            g_EB[((size_t)lane * S_ + t) * H_ + j] = hn;
        }
        buf ^= 1;
        grid_barrier();
    }

    // ---------------- load this block's enc_outs into SMEM (persists through decode) ----------------
    if (bx < B_) {
        const float* esrc = g_EB + (size_t)bx * S_ * H_;
        for (int i = tid; i < S_ * H_; i += NTHR) sE[i] = __ldcg(esrc + i);
    }

    // ---------------- decoder: 64 steps, 2 barriers each ----------------
    for (int t = 0; t < T_; t++) {
        // ---- phase 1: gh dots (all blocks) + attention/x (blocks 0..31) ----
        const float* hsrc = g_hT[buf];
        for (int i = tid; i < H_ * B_; i += NTHR) sh[i] = __ldcg(hsrc + i);
        __syncthreads();

        float ah = bhD;
#pragma unroll 4
        for (int q = 0; q < H_ / 4; q++) {
            float4 c = __ldg(whD + q);
            int base = q * 4 * B_ + lane;
            ah += c.x * sh[base] + c.y * sh[base + B_] + c.z * sh[base + 2 * B_] + c.w * sh[base + 3 * B_];
        }

        if (bx < B_) {                       // this block owns batch element b = bx
            const int b = bx;
            for (int jj = tid; jj < H_; jj += NTHR) shb[jj] = sh[jj * B_ + b];
            __syncthreads();
            // scores[s] = enc_outs[s,b,:] . h[b,:]
            for (int s = w; s < S_; s += 6) {
                float p = 0.f;
#pragma unroll
                for (int m = 0; m < 8; m++) { int jj = lane + 32 * m; p += sE[s * H_ + jj] * shb[jj]; }
                p = wred(p);
                if (lane == 0) satt[s] = p;
            }
            __syncthreads();
            if (w == 0) {                    // softmax over 64 scores
                float v0 = satt[lane], v1 = satt[lane + 32];
                float mx = wmax(fmaxf(v0, v1));
                float e0 = expf(v0 - mx), e1 = expf(v1 - mx);
                float ssum = wred(e0 + e1);
                satt[lane] = e0 / ssum; satt[lane + 32] = e1 / ssum;
            }
            if (w == 1 && t > 0) {           // prob for previous step (uses h = h_new of step t-1)
                int tok = inp_tok[b * T_ + (t - 1)];
                float p = 0.f;
#pragma unroll
                for (int m = 0; m < 8; m++) { int jj = lane + 32 * m; p += shb[jj] * __ldg(&W_out[(size_t)tok * H_ + jj]); }
                p = wred(p);
                if (lane == 0) g_probs[b * T_ + (t - 1)] = 1.f / (1.f + expf(-(p + b_out[tok])));
            }
            __syncthreads();
            // ctx[jj] = sum_s attn[s] * enc_outs[s,b,jj]
            for (int jj = tid; jj < H_; jj += NTHR) {
                float c = 0.f;
                for (int s = 0; s < S_; s++) c += satt[s] * sE[s * H_ + jj];
                sctx[jj] = c;
            }
            __syncthreads();
            // x[j'] = relu(c0[j'] + W_comb[j', H:2H] . ctx)
            for (int jp = w; jp < H_; jp += 6) {
                const float* wr = W_comb + (size_t)jp * (2 * H_) + H_;
                float p = 0.f;
#pragma unroll
                for (int m = 0; m < 8; m++) { int jj = lane + 32 * m; p += __ldg(wr + jj) * sctx[jj]; }
                p = wred(p);
                if (lane == 0) {
                    float xv = g_c0[jp] + p;
                    g_xT[jp * B_ + b] = xv > 0.f ? xv : 0.f;
                }
            }
        }
        grid_barrier();

        // ---- phase 2: gi dots + GRU combine ----
        for (int i = tid; i < H_ * B_; i += NTHR) sx[i] = __ldcg(g_xT + i);
        __syncthreads();
        float ai = biD;
#pragma unroll 4
        for (int q = 0; q < H_ / 4; q++) {
            float4 a = __ldg(wiD + q);
            int base = q * 4 * B_ + lane;
            ai += a.x * sx[base] + a.y * sx[base + B_] + a.z * sx[base + 2 * B_] + a.w * sx[base + 3 * B_];
        }
        sgi[w * 32 + lane] = ai; sgh[w * 32 + lane] = ah;
        __syncthreads();
        if (gate == 0) {
            float r = 1.f / (1.f + expf(-(sgi[w * 32 + lane] + sgh[w * 32 + lane])));
            float z = 1.f / (1.f + expf(-(sgi[(w + 1) * 32 + lane] + sgh[(w + 1) * 32 + lane])));
            float n = tanhf(sgi[(w + 2) * 32 + lane] + r * sgh[(w + 2) * 32 + lane]);
            float hold = sh[j * B_ + lane];   // sh still holds h_{t} from phase 1
            float hn = (1.f - z) * n + z * hold;
            g_hT[buf ^ 1][j * B_ + lane] = hn;
        }
        buf ^= 1;
        grid_barrier();
    }

    // ---------------- final-step prob ----------------
    if (bx < B_) {
        const int b = bx;
        for (int jj = tid; jj < H_; jj += NTHR) shb[jj] = __ldcg(&g_hT[buf][jj * B_ + b]);
        __syncthreads();
        if (w == 0) {
            int tok = inp_tok[b * T_ + (T_ - 1)];
            float p = 0.f;
#pragma unroll
            for (int m = 0; m < 8; m++) { int jj = lane + 32 * m; p += shb[jj] * __ldg(&W_out[(size_t)tok * H_ + jj]); }
            p = wred(p);
            if (lane == 0) g_probs[b * T_ + (T_ - 1)] = 1.f / (1.f + expf(-(p + b_out[tok])));
        }
    }
    grid_barrier();

    // ---------------- outputs: out[0] = loss, out[1..] = probs [B,T] ----------------
    for (int i = bx * NTHR + tid; i < B_ * T_; i += NBLK * NTHR) out[1 + i] = __ldcg(g_probs + i);
    if (bx == 0) {
        float tv = tsamp ? (float)(*tsamp) : 1.0f;
        float acc = 0.f;
        for (int i = tid; i < B_ * T_; i += NTHR) {
            float p  = __ldcg(g_probs + i);
            float lp = fmaxf(logf(p), -100.f);
            float l1 = fmaxf(log1pf(-p), -100.f);
            acc += tv * lp + (1.f - tv) * l1;
        }
        acc = wred(acc);
        if (lane == 0) sred[w] = acc;
        __syncthreads();
        if (tid == 0) {
            float s = 0.f;
            for (int u = 0; u < 6; u++) s += sred[u];
            out[0] = -s / (float)(B_ * T_);
        }
    }
}

extern "C" void kernel_launch(void* const* d_in, const int* in_sizes, int n_in,
                              void* d_out, int out_size) {
    (void)in_sizes; (void)out_size;
    const size_t smem = 33760 * sizeof(float);   // 135040 B
    cudaFuncSetAttribute(seq2seq_kernel, cudaFuncAttributeMaxDynamicSharedMemorySize, (int)smem);

    // Defensive input indexing: true_sample may or may not be materialized as a tensor.
    int base = (n_in >= 17) ? 3 : 2;
    const int* ts = (n_in >= 17) ? (const int*)d_in[2] : nullptr;

    seq2seq_kernel<<<NBLK, NTHR, smem>>>(
        (const int*)d_in[0], (const int*)d_in[1], ts,
        (const float*)d_in[base + 0],  // enc_emb
        (const float*)d_in[base + 1],  // enc_Wih
        (const float*)d_in[base + 2],  // enc_Whh
        (const float*)d_in[base + 3],  // enc_bih
        (const float*)d_in[base + 4],  // enc_bhh
        (const float*)d_in[base + 5],  // dec_emb
        (const float*)d_in[base + 6],  // W_comb
        (const float*)d_in[base + 7],  // b_comb
        (const float*)d_in[base + 8],  // dec_Wih
        (const float*)d_in[base + 9],  // dec_Whh
        (const float*)d_in[base + 10], // dec_bih
        (const float*)d_in[base + 11], // dec_bhh
        (const float*)d_in[base + 12], // W_out
        (const float*)d_in[base + 13], // b_out
        (float*)d_out);
}